// round 3
// baseline (speedup 1.0000x reference)
#include <cuda_runtime.h>
#include <cuda_bf16.h>

// ---------------------------------------------------------------------------
// NDCG loss, N = 16,777,216 (general N supported up to MAXG*EPB).
// Pass 1: score -> per-32-elem bitmask + per-block positive counts.
// Pass 2: predict + bitmask -> per-element term, per-block partial sums.
// Pass 3: deterministic reduction of partials -> d_out[0].
// ---------------------------------------------------------------------------

#define EPB 8192            // elements per block (256 thr * 32 elem)
#define EPW 1024            // elements per warp
#define MAXG 4096           // max blocks supported by static scratch

__device__ unsigned int g_mask[MAXG * 256];   // 1 bit per element
__device__ int          g_counts[MAXG];       // positives per block
__device__ float        g_partials[MAXG];     // per-block loss partials

// ---------------------------------------------------------------------------
__global__ __launch_bounds__(256) void k_mask(const float* __restrict__ score,
                                              int N) {
    const int warp = threadIdx.x >> 5, lane = threadIdx.x & 31;
    const int base = blockIdx.x * EPB + warp * EPW;

    // Warp covers EPW=1024 elements -> 32 mask words; lane L owns word L.
    unsigned myword = 0;
    #pragma unroll
    for (int j = 0; j < 32; ++j) {
        int idx = base + j * 32 + lane;
        float v = (idx < N) ? score[idx] : 0.0f;
        unsigned b = __ballot_sync(0xffffffffu, v > 0.0f);
        if (lane == j) myword = b;
    }
    g_mask[(blockIdx.x << 8) + (warp << 5) + lane] = myword;

    int c = __popc(myword);
    #pragma unroll
    for (int o = 16; o; o >>= 1) c += __shfl_xor_sync(0xffffffffu, c, o);

    __shared__ int sc[8];
    if (lane == 0) sc[warp] = c;
    __syncthreads();
    if (threadIdx.x == 0) {
        int t = 0;
        #pragma unroll
        for (int w = 0; w < 8; ++w) t += sc[w];
        g_counts[blockIdx.x] = t;
    }
}

// ---------------------------------------------------------------------------
__global__ __launch_bounds__(256) void k_loss(const float* __restrict__ pred,
                                              int N, int G) {
    const int tid  = threadIdx.x;
    const int warp = tid >> 5, lane = tid & 31;

    // --- exclusive block prefix of positives + total P (counts array is tiny,
    //     L2-hot: each block re-reduces it) ---
    int pre = 0, tot = 0;
    for (int i = tid; i < G; i += 256) {
        int c = g_counts[i];
        tot += c;
        pre += (i < (int)blockIdx.x) ? c : 0;
    }
    #pragma unroll
    for (int o = 16; o; o >>= 1) {
        pre += __shfl_xor_sync(0xffffffffu, pre, o);
        tot += __shfl_xor_sync(0xffffffffu, tot, o);
    }
    __shared__ int spre[8], stot[8], wsum[8];
    if (lane == 0) { spre[warp] = pre; stot[warp] = tot; }
    __syncthreads();
    int blockPre = 0, P = 0;
    #pragma unroll
    for (int w = 0; w < 8; ++w) { blockPre += spre[w]; P += stot[w]; }

    // --- per-warp mask words + intra-warp positive prefix via popc scan ---
    const int base = blockIdx.x * EPB + warp * EPW;
    unsigned myword = g_mask[(blockIdx.x << 8) + (warp << 5) + lane];
    int wc  = __popc(myword);
    int inc = wc;
    #pragma unroll
    for (int o = 1; o < 32; o <<= 1) {
        int t = __shfl_up_sync(0xffffffffu, inc, o);
        if (lane >= o) inc += t;
    }
    int exc = inc - wc;                 // positives before word 'lane' in warp
    if (lane == 31) wsum[warp] = inc;   // warp total
    __syncthreads();
    int warpBase = blockPre;
    for (int w = 0; w < warp; ++w) warpBase += wsum[w];

    const float Pf    = (float)P;
    const float invP  = 1.0f / Pf;          // s value at positives
    const float sum_s = Pf * invP;          // ~= 1.0 (faithful to reference)
    const float rp    = 1.0f / sum_s;

    float acc = 0.0f;

    #pragma unroll
    for (int j = 0; j < 8; ++j) {
        int e0 = base + j * 128 + lane * 4;       // this thread's 4 elements
        float4 pv;
        if (e0 + 3 < N) {
            pv = *reinterpret_cast<const float4*>(pred + e0);
        } else {
            pv.x = (e0     < N) ? pred[e0]     : 0.0f;
            pv.y = (e0 + 1 < N) ? pred[e0 + 1] : 0.0f;
            pv.z = (e0 + 2 < N) ? pred[e0 + 2] : 0.0f;
            pv.w = (e0 + 3 < N) ? pred[e0 + 3] : 0.0f;
        }
        const int wl = j * 4 + (lane >> 3);       // word covering these elems
        const unsigned w = __shfl_sync(0xffffffffu, myword, wl);
        const int pe     = __shfl_sync(0xffffffffu, exc,    wl);
        const int kb0    = warpBase + pe;
        const int bit0   = (lane & 7) * 4;
        float pvals[4] = {pv.x, pv.y, pv.z, pv.w};

        #pragma unroll
        for (int c = 0; c < 4; ++c) {
            int idx = e0 + c;
            int bit = bit0 + c;
            int kb  = kb0 + __popc(w & ((1u << bit) - 1u)); // exclusive k
            float p = pvals[c] * rp;
            float term;
            if ((w >> bit) & 1u) {
                float kf = (float)(kb + 1);                 // inclusive rank
                float lg = __log2f(kf + 1.0f);
                float d  = __fdividef(p, kf + 1.0f) - __fdividef(invP, lg);
                term = d * d;
            } else {
                float mf = (float)(idx + 1 - kb);           // inclusive neg rank
                float q  = __fdividef(p, Pf + mf + 1.0f);
                term = q * q;
            }
            if (idx < N) acc += term;
        }
    }

    #pragma unroll
    for (int o = 16; o; o >>= 1) acc += __shfl_xor_sync(0xffffffffu, acc, o);
    __shared__ float sacc[8];
    if (lane == 0) sacc[warp] = acc;
    __syncthreads();
    if (tid == 0) {
        float t = 0.0f;
        #pragma unroll
        for (int w = 0; w < 8; ++w) t += sacc[w];
        g_partials[blockIdx.x] = t;
    }
}

// ---------------------------------------------------------------------------
__global__ __launch_bounds__(256) void k_final(float* __restrict__ out, int G) {
    int tid = threadIdx.x;
    float a = 0.0f;
    for (int i = tid; i < G; i += 256) a += g_partials[i];
    #pragma unroll
    for (int o = 16; o; o >>= 1) a += __shfl_xor_sync(0xffffffffu, a, o);
    __shared__ float s[8];
    if ((tid & 31) == 0) s[tid >> 5] = a;
    __syncthreads();
    if (tid == 0) {
        float t = 0.0f;
        #pragma unroll
        for (int w = 0; w < 8; ++w) t += s[w];
        out[0] = t;
    }
}

// ---------------------------------------------------------------------------
extern "C" void kernel_launch(void* const* d_in, const int* in_sizes, int n_in,
                              void* d_out, int out_size) {
    const float* pred  = (const float*)d_in[0];  // predict_score
    const float* score = (const float*)d_in[1];  // score (0/1)
    int N = in_sizes[0];
    int G = (N + EPB - 1) / EPB;
    if (G > MAXG) G = MAXG;   // problem size is 2^24 -> G = 2048

    k_mask<<<G, 256>>>(score, N);
    k_loss<<<G, 256>>>(pred, N, G);
    k_final<<<1, 256>>>((float*)d_out, G);
}

// round 4
// speedup vs baseline: 1.2291x; 1.2291x over previous
#include <cuda_runtime.h>
#include <cuda_bf16.h>

// ---------------------------------------------------------------------------
// NDCG loss, N = 16,777,216 (general N supported up to MAXG*EPB).
// Pass 1: score -> per-32-elem bitmask + per-block positive counts.
//         (loads batched x8 for MLP; pass is DRAM-bound)
// Pass 2: predict + bitmask -> per-element term, per-block partial sums.
//         (branch-free unified term: 1 log2 + 1 divide per element)
// Pass 3: deterministic reduction of partials -> d_out[0].
// ---------------------------------------------------------------------------

#define EPB 8192            // elements per block (256 thr * 32 elem)
#define EPW 1024            // elements per warp
#define MAXG 4096           // max blocks supported by static scratch

__device__ unsigned int g_mask[MAXG * 256];   // 1 bit per element
__device__ int          g_counts[MAXG];       // positives per block
__device__ float        g_partials[MAXG];     // per-block loss partials

// ---------------------------------------------------------------------------
__global__ __launch_bounds__(256) void k_mask(const float* __restrict__ score,
                                              int N) {
    const int warp = threadIdx.x >> 5, lane = threadIdx.x & 31;
    const int base = blockIdx.x * EPB + warp * EPW;

    // Warp covers EPW=1024 elements -> 32 mask words; lane L owns word L.
    // Loads batched 8 at a time so ptxas front-batches them (MLP_p1 = 8).
    unsigned myword = 0;
    #pragma unroll
    for (int j0 = 0; j0 < 32; j0 += 8) {
        float v[8];
        #pragma unroll
        for (int t = 0; t < 8; ++t) {
            int idx = base + (j0 + t) * 32 + lane;
            v[t] = (idx < N) ? score[idx] : 0.0f;
        }
        #pragma unroll
        for (int t = 0; t < 8; ++t) {
            unsigned b = __ballot_sync(0xffffffffu, v[t] > 0.0f);
            if (lane == j0 + t) myword = b;
        }
    }
    g_mask[(blockIdx.x << 8) + (warp << 5) + lane] = myword;

    int c = __popc(myword);
    #pragma unroll
    for (int o = 16; o; o >>= 1) c += __shfl_xor_sync(0xffffffffu, c, o);

    __shared__ int sc[8];
    if (lane == 0) sc[warp] = c;
    __syncthreads();
    if (threadIdx.x == 0) {
        int t = 0;
        #pragma unroll
        for (int w = 0; w < 8; ++w) t += sc[w];
        g_counts[blockIdx.x] = t;
    }
}

// ---------------------------------------------------------------------------
__global__ __launch_bounds__(256) void k_loss(const float* __restrict__ pred,
                                              int N, int G) {
    const int tid  = threadIdx.x;
    const int warp = tid >> 5, lane = tid & 31;

    // --- exclusive block prefix of positives + total P (counts array is tiny,
    //     L2-hot: each block re-reduces it) ---
    int pre = 0, tot = 0;
    for (int i = tid; i < G; i += 256) {
        int c = g_counts[i];
        tot += c;
        pre += (i < (int)blockIdx.x) ? c : 0;
    }
    #pragma unroll
    for (int o = 16; o; o >>= 1) {
        pre += __shfl_xor_sync(0xffffffffu, pre, o);
        tot += __shfl_xor_sync(0xffffffffu, tot, o);
    }
    __shared__ int spre[8], stot[8], wsum[8];
    if (lane == 0) { spre[warp] = pre; stot[warp] = tot; }
    __syncthreads();
    int blockPre = 0, P = 0;
    #pragma unroll
    for (int w = 0; w < 8; ++w) { blockPre += spre[w]; P += stot[w]; }

    // --- per-warp mask words + intra-warp positive prefix via popc scan ---
    const int base = blockIdx.x * EPB + warp * EPW;
    unsigned myword = g_mask[(blockIdx.x << 8) + (warp << 5) + lane];
    int wc  = __popc(myword);
    int inc = wc;
    #pragma unroll
    for (int o = 1; o < 32; o <<= 1) {
        int t = __shfl_up_sync(0xffffffffu, inc, o);
        if (lane >= o) inc += t;
    }
    int exc = inc - wc;                 // positives before word 'lane' in warp
    if (lane == 31) wsum[warp] = inc;   // warp total
    __syncthreads();
    int warpBase = blockPre;
    for (int w = 0; w < warp; ++w) warpBase += wsum[w];

    const float Pf    = (float)P;
    const float invP  = 1.0f / Pf;          // s value at positives
    const float sum_s = Pf * invP;          // ~= 1.0 (faithful to reference)
    const float rp    = 1.0f / sum_s;

    float acc = 0.0f;

    // Process 8 groups of 128 elems; pred loads batched 4 float4 at a time.
    #pragma unroll
    for (int jb = 0; jb < 8; jb += 4) {
        float4 pv[4];
        #pragma unroll
        for (int t = 0; t < 4; ++t) {
            int e0 = base + (jb + t) * 128 + lane * 4;
            if (e0 + 3 < N) {
                pv[t] = *reinterpret_cast<const float4*>(pred + e0);
            } else {
                pv[t].x = (e0     < N) ? pred[e0]     : 0.0f;
                pv[t].y = (e0 + 1 < N) ? pred[e0 + 1] : 0.0f;
                pv[t].z = (e0 + 2 < N) ? pred[e0 + 2] : 0.0f;
                pv[t].w = (e0 + 3 < N) ? pred[e0 + 3] : 0.0f;
            }
        }
        #pragma unroll
        for (int t = 0; t < 4; ++t) {
            const int j  = jb + t;
            const int e0 = base + j * 128 + lane * 4;
            const int wl = j * 4 + (lane >> 3);      // word covering these elems
            const unsigned w = __shfl_sync(0xffffffffu, myword, wl);
            const int pe     = __shfl_sync(0xffffffffu, exc,    wl);
            const int kb0    = warpBase + pe;
            const int bit0   = (lane & 7) * 4;
            const int kbase  = kb0 + __popc(w & ((1u << bit0) - 1u));
            float pvals[4] = {pv[t].x, pv[t].y, pv[t].z, pv[t].w};

            int kb = kbase;                          // exclusive positive count
            #pragma unroll
            for (int c = 0; c < 4; ++c) {
                const int idx = e0 + c;
                const int bit = bit0 + c;
                const bool pos = (w >> bit) & 1u;
                const float p = pvals[c] * rp;
                // Unified term:
                //  pos: A = k+1 (k = kb+1 inclusive), C = log2(A), sel = invP
                //       d = (p*C - invP*A)/(A*C) = p/(k+1) - invP/log2(k+1)
                //  neg: A = P+m+1 (m = idx+1-kb inclusive), C = 1, sel = 0
                //       d = p/A
                const float A   = pos ? (float)(kb + 2)
                                      : (Pf + (float)(idx + 2 - kb));
                const float C   = pos ? __log2f(A) : 1.0f;
                const float sel = pos ? invP : 0.0f;
                const float num = p * C - sel * A;
                const float d   = __fdividef(num, A * C);
                if (idx < N) acc += d * d;
                kb += pos ? 1 : 0;
            }
        }
    }

    #pragma unroll
    for (int o = 16; o; o >>= 1) acc += __shfl_xor_sync(0xffffffffu, acc, o);
    __shared__ float sacc[8];
    if (lane == 0) sacc[warp] = acc;
    __syncthreads();
    if (tid == 0) {
        float t = 0.0f;
        #pragma unroll
        for (int w = 0; w < 8; ++w) t += sacc[w];
        g_partials[blockIdx.x] = t;
    }
}

// ---------------------------------------------------------------------------
__global__ __launch_bounds__(256) void k_final(float* __restrict__ out, int G) {
    int tid = threadIdx.x;
    float a = 0.0f;
    for (int i = tid; i < G; i += 256) a += g_partials[i];
    #pragma unroll
    for (int o = 16; o; o >>= 1) a += __shfl_xor_sync(0xffffffffu, a, o);
    __shared__ float s[8];
    if ((tid & 31) == 0) s[tid >> 5] = a;
    __syncthreads();
    if (tid == 0) {
        float t = 0.0f;
        #pragma unroll
        for (int w = 0; w < 8; ++w) t += s[w];
        out[0] = t;
    }
}

// ---------------------------------------------------------------------------
extern "C" void kernel_launch(void* const* d_in, const int* in_sizes, int n_in,
                              void* d_out, int out_size) {
    const float* pred  = (const float*)d_in[0];  // predict_score
    const float* score = (const float*)d_in[1];  // score (0/1)
    int N = in_sizes[0];
    int G = (N + EPB - 1) / EPB;
    if (G > MAXG) G = MAXG;   // problem size is 2^24 -> G = 2048

    k_mask<<<G, 256>>>(score, N);
    k_loss<<<G, 256>>>(pred, N, G);
    k_final<<<1, 256>>>((float*)d_out, G);
}